// round 8
// baseline (speedup 1.0000x reference)
#include <cuda_runtime.h>
#include <cuda_bf16.h>
#include <cstdint>

// ---------------------------------------------------------------------------
// Sizes (fixed by the problem)
// ---------------------------------------------------------------------------
#define BATCH    256
#define NAGENTS  8192
#define NEDGES   262144
#define ACT      21

#define L2E 1.4426950408889634f
#define LN2 0.6931471805599453f

// ---------------------------------------------------------------------------
// Scratch (device globals: no allocation allowed)
// ---------------------------------------------------------------------------
__device__ float  g_h2[BATCH * 1024];         // conv2 out, flattened
__device__ float  g_hidden[BATCH * 512];      // fc out
__device__ float  g_enc[NAGENTS];             // actor_encoding[0]
__device__ float  g_deg[NAGENTS];
__device__ float  g_dinv[NAGENTS];
__device__ float2 g_AB[NAGENTS];              // rank-2 gcn1 aggregates
__device__ float  g_g1[NAGENTS * 16];
__device__ float  g_s[NAGENTS * 16];          // gcn2 input aggregates
__device__ float  g_w2sum[16];
__device__ float  g_b2mean;

// ---------------------------------------------------------------------------
// helpers
// ---------------------------------------------------------------------------
__device__ __forceinline__ unsigned long long fma2(unsigned long long a,
                                                   unsigned long long b,
                                                   unsigned long long c) {
    unsigned long long d;
    asm("fma.rn.f32x2 %0, %1, %2, %3;" : "=l"(d) : "l"(a), "l"(b), "l"(c));
    return d;
}
__device__ __forceinline__ unsigned long long dup2(float v) {
    unsigned u = __float_as_uint(v);
    return ((unsigned long long)u << 32) | (unsigned long long)u;
}
__device__ __forceinline__ unsigned long long pack2(float lo, float hi) {
    return ((unsigned long long)__float_as_uint(hi) << 32) |
           (unsigned long long)__float_as_uint(lo);
}
__device__ __forceinline__ float flo(unsigned long long v) {
    return __uint_as_float((unsigned)v);
}
__device__ __forceinline__ float fhi(unsigned long long v) {
    return __uint_as_float((unsigned)(v >> 32));
}
__device__ __forceinline__ float ex2(float v) {
    float r;
    asm("ex2.approx.ftz.f32 %0, %1;" : "=f"(r) : "f"(v));
    return r;
}

// ---------------------------------------------------------------------------
// Fused conv1+conv2 per batch element. One CTA per batch.
//  conv1: x[5,13,13] -> h1[32,6,6]   (3x3 s2, relu)  in SMEM
//  conv2: h1 -> h2[64,4,4] -> g_h2[b,1024] (3x3 s1, relu)
// conv2 weights staged in SMEM with [j][oc] layout, row stride 65 (no bank
// conflicts on either the staging writes or the broadcast reads).
// ---------------------------------------------------------------------------
#define CV_XS    0
#define CV_H1    848
#define CV_W2    2000
#define CV_FLOATS (2000 + 288 * 65)
#define CV_SMEM   (CV_FLOATS * 4)

__global__ void __launch_bounds__(256) k_convs(const float* __restrict__ x,
                                               const float* __restrict__ c1w,
                                               const float* __restrict__ c1b,
                                               const float* __restrict__ c2w,
                                               const float* __restrict__ c2b) {
    extern __shared__ float sm[];
    float* xs  = sm + CV_XS;
    float* h1s = sm + CV_H1;
    float* w2s = sm + CV_W2;
    const int b = blockIdx.x, tid = threadIdx.x;

    for (int i = tid; i < 845; i += 256) xs[i] = x[b * 845 + i];
    for (int i = tid; i < 64 * 288; i += 256) {
        int oc = i / 288, j = i % 288;
        w2s[j * 65 + oc] = c2w[i];
    }
    __syncthreads();

    // conv1
    for (int idx = tid; idx < 1152; idx += 256) {
        int oc = idx / 36, p = idx % 36;
        int oy = p / 6, ox = p % 6;
        const float* wb = c1w + oc * 45;
        float acc = c1b[oc];
#pragma unroll
        for (int ic = 0; ic < 5; ic++)
#pragma unroll
            for (int ky = 0; ky < 3; ky++)
#pragma unroll
                for (int kx = 0; kx < 3; kx++)
                    acc += xs[ic * 169 + (2 * oy + ky) * 13 + 2 * ox + kx] *
                           wb[ic * 9 + ky * 3 + kx];
        h1s[idx] = fmaxf(acc, 0.0f);
    }
    __syncthreads();

    // conv2: thread -> (oc = tid/4, oy = tid%4), 4 outputs along ox
    int oc = tid >> 2, oy = tid & 3;
    float bias = c2b[oc];
    float acc[4];
#pragma unroll
    for (int q = 0; q < 4; q++) acc[q] = bias;

    for (int ic = 0; ic < 32; ic++) {
#pragma unroll
        for (int ky = 0; ky < 3; ky++) {
            const float* row = &h1s[ic * 36 + (oy + ky) * 6];
            float r0 = row[0], r1 = row[1], r2 = row[2];
            float r3 = row[3], r4 = row[4], r5 = row[5];
            const float* wr = &w2s[(ic * 9 + ky * 3) * 65 + oc];
            float w0 = wr[0], w1 = wr[65], w2 = wr[130];
            acc[0] += r0 * w0 + r1 * w1 + r2 * w2;
            acc[1] += r1 * w0 + r2 * w1 + r3 * w2;
            acc[2] += r2 * w0 + r3 * w1 + r4 * w2;
            acc[3] += r3 * w0 + r4 * w1 + r5 * w2;
        }
    }
    float* o = g_h2 + b * 1024 + oc * 16 + oy * 4;
#pragma unroll
    for (int q = 0; q < 4; q++) o[q] = fmaxf(acc[q], 0.0f);
}

// ---------------------------------------------------------------------------
// fc: hidden = relu(h2 @ fc_w^T + fc_b).
// Grid: 16 rowgroups x 32 colgroups. CTA 512 threads = 16 warps, one warp per
// output column; lanes split K (coalesced fc_w float4 loads).
// h2 rowgroup (16 x 1024 f) staged in 64KB dynamic SMEM.
// ---------------------------------------------------------------------------
#define FC_SMEM (16 * 1024 * 4)

__global__ void __launch_bounds__(512) k_fc(const float* __restrict__ fc_w,
                                            const float* __restrict__ fc_b) {
    extern __shared__ float sm[];
    const int tid = threadIdx.x, wid = tid >> 5, lane = tid & 31;
    const int rg = blockIdx.x >> 5;   // 0..15
    const int cg = blockIdx.x & 31;   // 0..31
    const int row0 = rg * 16;

    const float4* src = (const float4*)(g_h2 + row0 * 1024);
    float4* dst = (float4*)sm;
#pragma unroll
    for (int i = 0; i < 8; i++) dst[tid + i * 512] = src[tid + i * 512];
    __syncthreads();

    const int col = cg * 16 + wid;
    const float4* w4 = (const float4*)(fc_w + col * 1024);
    const float4* h4 = (const float4*)sm;

    unsigned long long acc[16];
#pragma unroll
    for (int r = 0; r < 16; r++) acc[r] = 0ull;

#pragma unroll
    for (int it = 0; it < 8; it++) {
        float4 w = w4[lane + it * 32];
        unsigned long long wa = pack2(w.x, w.y);
        unsigned long long wb = pack2(w.z, w.w);
#pragma unroll
        for (int r = 0; r < 16; r++) {
            float4 h = h4[r * 256 + lane + it * 32];
            acc[r] = fma2(wa, pack2(h.x, h.y), acc[r]);
            acc[r] = fma2(wb, pack2(h.z, h.w), acc[r]);
        }
    }
    float bias = fc_b[col];
#pragma unroll
    for (int r = 0; r < 16; r++) {
        float v = flo(acc[r]) + fhi(acc[r]);
#pragma unroll
        for (int o = 16; o; o >>= 1) v += __shfl_xor_sync(0xffffffffu, v, o);
        if (lane == 0)
            g_hidden[(row0 + r) * 512 + col] = fmaxf(v + bias, 0.0f);
    }
}

// ---------------------------------------------------------------------------
// logits + categorical log_prob / entropy; writes action as float.
// One CTA (256 thr) per batch row; warp w handles actions {w, w+8, w+16}.
// Output layout: [action(256) | msg_out(8192) | log_prob(256) | entropy(256)]
// ---------------------------------------------------------------------------
__global__ void __launch_bounds__(256) k_logits(const float* __restrict__ muw,
                                                const float* __restrict__ mub,
                                                const int* __restrict__ action,
                                                float* __restrict__ out) {
    __shared__ float hs[512];
    __shared__ float lg[24];
    const int bb = blockIdx.x, tid = threadIdx.x;
    const int wid = tid >> 5, lane = tid & 31;

    ((float2*)hs)[tid] = ((const float2*)(g_hidden + bb * 512))[tid];
    __syncthreads();

    const float4* h4 = (const float4*)hs;
    for (int a = wid; a < ACT; a += 8) {
        const float4* wr = (const float4*)(muw + a * 512);
        float acc = 0.0f;
#pragma unroll
        for (int i = 0; i < 4; i++) {
            float4 w = wr[lane + i * 32];
            float4 h = h4[lane + i * 32];
            acc += w.x * h.x + w.y * h.y + w.z * h.z + w.w * h.w;
        }
#pragma unroll
        for (int o = 16; o; o >>= 1) acc += __shfl_xor_sync(0xffffffffu, acc, o);
        if (lane == 0) lg[a] = acc + mub[a];
    }
    __syncthreads();

    if (wid == 0) {
        float l = (lane < ACT) ? lg[lane] : -3.4e38f;
        float m = l;
#pragma unroll
        for (int o = 16; o; o >>= 1)
            m = fmaxf(m, __shfl_xor_sync(0xffffffffu, m, o));
        float e  = (lane < ACT) ? __expf(l - m) : 0.0f;
        float el = (lane < ACT) ? e * l : 0.0f;
        float se = e, sel = el;
#pragma unroll
        for (int o = 16; o; o >>= 1) {
            se  += __shfl_xor_sync(0xffffffffu, se, o);
            sel += __shfl_xor_sync(0xffffffffu, sel, o);
        }
        int a = action[bb];
        float la = __shfl_sync(0xffffffffu, l, a);
        if (lane == 0) {
            float lse = m + __logf(se);
            out[BATCH + NAGENTS + bb]     = la - lse;        // log_prob
            out[2 * BATCH + NAGENTS + bb] = lse - sel / se;  // entropy
            out[bb] = (float)a;                              // action
        }
    }
}

// ---------------------------------------------------------------------------
// actor_encoding row 0: enc[j] = hidden[0] . msg_w[j] + msg_b[j]. Warp-dot.
// ---------------------------------------------------------------------------
__global__ void __launch_bounds__(256) k_enc(const float* __restrict__ msg_w,
                                             const float* __restrict__ msg_b) {
    int gtid = blockIdx.x * 256 + threadIdx.x;
    int j    = gtid >> 5;
    int lane = gtid & 31;
    if (j >= NAGENTS) return;
    const float4* w4 = (const float4*)(msg_w + j * 512);
    const float4* h4 = (const float4*)g_hidden;
    float acc = 0.0f;
#pragma unroll
    for (int i = 0; i < 4; i++) {
        float4 w = w4[lane + i * 32];
        float4 h = h4[lane + i * 32];
        acc += w.x * h.x + w.y * h.y + w.z * h.z + w.w * h.w;
    }
#pragma unroll
    for (int o = 16; o; o >>= 1) acc += __shfl_xor_sync(0xffffffffu, acc, o);
    if (lane == 0) g_enc[j] = acc + msg_b[j];
}

// ---------------------------------------------------------------------------
// blocks 0-15: colsum(W2); block 16: mean(b2); blocks 17-48: deg init.
// ---------------------------------------------------------------------------
__global__ void k_w2sum(const float* __restrict__ W2,
                        const float* __restrict__ b2) {
    int tid = threadIdx.x;
    int k   = blockIdx.x;
    if (k >= 17) {
        int i = (k - 17) * 256 + tid;
        if (i < NAGENTS) g_deg[i] = 1.0f;   // self loop
        return;
    }
    __shared__ float red[256];
    const float* src = (k < 16) ? (W2 + k * NAGENTS) : b2;
    float acc = 0.0f;
    for (int j = tid; j < NAGENTS; j += 256) acc += src[j];
    red[tid] = acc;
    __syncthreads();
    for (int s = 128; s; s >>= 1) {
        if (tid < s) red[tid] += red[tid + s];
        __syncthreads();
    }
    if (tid == 0) {
        if (k < 16) g_w2sum[k] = red[0];
        else        g_b2mean  = red[0] * (1.0f / (float)NAGENTS);
    }
}

// ---------------------------------------------------------------------------
// GCN norm + aggregation
// ---------------------------------------------------------------------------
__global__ void k_deg(const int* __restrict__ ei) {
    int e = blockIdx.x * 256 + threadIdx.x;
    if (e < NEDGES) atomicAdd(&g_deg[ei[2 * e + 1]], 1.0f);
}
__global__ void k_dinvAB(const float* __restrict__ xm) {
    int i = blockIdx.x * 256 + threadIdx.x;
    if (i >= NAGENTS) return;
    float dv = rsqrtf(g_deg[i]);
    g_dinv[i] = dv;
    float d2 = dv * dv;                       // self-loop norm
    g_AB[i] = make_float2(d2 * xm[i], d2 * g_enc[i]);
}
__global__ void k_edge1(const int* __restrict__ ei,
                        const float* __restrict__ xm) {
    int e = blockIdx.x * 256 + threadIdx.x;
    if (e >= NEDGES) return;
    int s = ei[2 * e], d = ei[2 * e + 1];
    float nrm = g_dinv[s] * g_dinv[d];
    atomicAdd(&g_AB[d].x, nrm * xm[s]);
    atomicAdd(&g_AB[d].y, nrm * g_enc[s]);
}
// g1 = relu(AB @ W1 + b1); s initialized with the self-loop term d^2 * g1
__global__ void k_g1s(const float* __restrict__ w1,
                      const float* __restrict__ b1) {
    int idx = blockIdx.x * 256 + threadIdx.x;
    if (idx >= NAGENTS * 16) return;
    int i = idx >> 4, k = idx & 15;
    float2 ab = g_AB[i];
    float v = fmaxf(ab.x * w1[k] + ab.y * w1[16 + k] + b1[k], 0.0f);
    g_g1[idx] = v;
    float dv = g_dinv[i];
    g_s[idx] = dv * dv * v;
}
__global__ void k_edge2(const int* __restrict__ ei) {
    int e = blockIdx.x * 256 + threadIdx.x;
    if (e >= NEDGES) return;
    int s = ei[2 * e], d = ei[2 * e + 1];
    float nrm = g_dinv[s] * g_dinv[d];
    const float4* g1r = (const float4*)(g_g1 + s * 16);
    float* sd = g_s + d * 16;
#pragma unroll
    for (int q = 0; q < 4; q++) {
        float4 v = g1r[q];
        atomicAdd(sd + q * 4 + 0, nrm * v.x);
        atomicAdd(sd + q * 4 + 1, nrm * v.y);
        atomicAdd(sd + q * 4 + 2, nrm * v.z);
        atomicAdd(sd + q * 4 + 3, nrm * v.w);
    }
}

// ---------------------------------------------------------------------------
// K12: msg_out[i] = mean_j(g_ij) - lse_j(g_ij) with g_ij = s[i].W2[:,j]+b2[j].
// 16 rows/CTA, W2 streamed in 16x1024 SMEM chunks, f32x2 FMA.
// Values computed in log2 domain (s, b2 pre-scaled by log2 e) -> raw ex2
// accumulation, no max-tracking needed (|g| << 80 analytically).
// ---------------------------------------------------------------------------
#define MS_CHUNK 1024
#define MS_ROWS  16
#define MS_SMEM  (16 * MS_CHUNK * 4 + MS_ROWS * 16 * 8)

__global__ void __launch_bounds__(256) k_msgout(const float* __restrict__ W2,
                                                const float* __restrict__ b2,
                                                float* __restrict__ out) {
    extern __shared__ char smraw[];
    float* wsm = (float*)smraw;                                    // 16*1024 f
    unsigned long long* sdup =
        (unsigned long long*)(smraw + 16 * MS_CHUNK * 4);          // 256 u64

    const int tid  = threadIdx.x;
    const int row0 = blockIdx.x * MS_ROWS;

    {   // duplicated, log2e-scaled s values for f32x2 broadcast
        int r = tid >> 4, k = tid & 15;
        sdup[tid] = dup2(g_s[(row0 + r) * 16 + k] * L2E);
    }

    float sr[MS_ROWS];
#pragma unroll
    for (int r = 0; r < MS_ROWS; r++) sr[r] = 0.0f;

    const float4* gw4 = (const float4*)W2;

    for (int chunk = 0; chunk < NAGENTS / MS_CHUNK; chunk++) {
        int base = chunk * MS_CHUNK;
        __syncthreads();
#pragma unroll
        for (int k = 0; k < 16; k++)
            ((float4*)wsm)[k * 256 + tid] = gw4[(k * NAGENTS + base) / 4 + tid];
        float4 bb = ((const float4*)(b2 + base))[tid];
        __syncthreads();

        unsigned long long acc0[MS_ROWS], acc1[MS_ROWS];
        unsigned long long b01 = pack2(bb.x * L2E, bb.y * L2E);
        unsigned long long b23 = pack2(bb.z * L2E, bb.w * L2E);
#pragma unroll
        for (int r = 0; r < MS_ROWS; r++) { acc0[r] = b01; acc1[r] = b23; }

        const ulonglong2* wU2 = (const ulonglong2*)wsm;
#pragma unroll
        for (int k = 0; k < 16; k++) {
            ulonglong2 w = wU2[k * 256 + tid];    // LDS.128, conflict-free
#pragma unroll
            for (int r = 0; r < MS_ROWS; r++) {
                unsigned long long sv = sdup[r * 16 + k];  // broadcast
                acc0[r] = fma2(w.x, sv, acc0[r]);
                acc1[r] = fma2(w.y, sv, acc1[r]);
            }
        }
#pragma unroll
        for (int r = 0; r < MS_ROWS; r++) {
            sr[r] += ex2(flo(acc0[r])) + ex2(fhi(acc0[r])) +
                     ex2(flo(acc1[r])) + ex2(fhi(acc1[r]));
        }
    }

    // block sum-reduce per row; alias onto wsm (16KB)
    __syncthreads();
    float* rs = wsm;              // [16][256]
#pragma unroll
    for (int r = 0; r < MS_ROWS; r++) rs[r * 256 + tid] = sr[r];
    for (int step = 128; step > 0; step >>= 1) {
        __syncthreads();
        if (tid < step) {
#pragma unroll
            for (int r = 0; r < MS_ROWS; r++)
                rs[r * 256 + tid] += rs[r * 256 + tid + step];
        }
    }
    __syncthreads();
    if (tid < MS_ROWS) {
        int row = row0 + tid;
        float lse = LN2 * __log2f(rs[tid * 256]);
        float acc = 0.0f;
#pragma unroll
        for (int k = 0; k < 16; k++) acc += g_s[row * 16 + k] * g_w2sum[k];
        out[BATCH + row] = acc * (1.0f / (float)NAGENTS) + g_b2mean - lse;
    }
}

// ---------------------------------------------------------------------------
// launch
// ---------------------------------------------------------------------------
extern "C" void kernel_launch(void* const* d_in, const int* in_sizes, int n_in,
                              void* d_out, int out_size) {
    const float* x    = (const float*)d_in[0];
    const float* xmsg = (const float*)d_in[1];
    const int*   ei   = (const int*)d_in[2];
    const int*   act  = (const int*)d_in[3];
    const float* c1w  = (const float*)d_in[4];
    const float* c1b  = (const float*)d_in[5];
    const float* c2w  = (const float*)d_in[6];
    const float* c2b  = (const float*)d_in[7];
    const float* fcw  = (const float*)d_in[8];
    const float* fcb  = (const float*)d_in[9];
    const float* muw  = (const float*)d_in[10];
    const float* mub  = (const float*)d_in[11];
    const float* msw  = (const float*)d_in[12];
    const float* msb  = (const float*)d_in[13];
    const float* g1w  = (const float*)d_in[14];
    const float* g1b  = (const float*)d_in[15];
    const float* g2w  = (const float*)d_in[16];
    const float* g2b  = (const float*)d_in[17];
    float* out = (float*)d_out;

    cudaFuncSetAttribute(k_convs, cudaFuncAttributeMaxDynamicSharedMemorySize,
                         CV_SMEM);
    cudaFuncSetAttribute(k_fc, cudaFuncAttributeMaxDynamicSharedMemorySize,
                         FC_SMEM);
    cudaFuncSetAttribute(k_msgout, cudaFuncAttributeMaxDynamicSharedMemorySize,
                         MS_SMEM);

    // GCN preprocessing independent of the CNN
    k_w2sum<<<49, 256>>>(g2w, g2b);
    k_deg<<<NEDGES / 256, 256>>>(ei);

    // CNN / actor head
    k_convs<<<BATCH, 256, CV_SMEM>>>(x, c1w, c1b, c2w, c2b);
    k_fc<<<512, 512, FC_SMEM>>>(fcw, fcb);
    k_logits<<<BATCH, 256>>>(muw, mub, act, out);
    k_enc<<<NAGENTS / 8, 256>>>(msw, msb);

    // GCN
    k_dinvAB<<<NAGENTS / 256, 256>>>(xmsg);
    k_edge1<<<NEDGES / 256, 256>>>(ei, xmsg);
    k_g1s<<<NAGENTS * 16 / 256, 256>>>(g1w, g1b);
    k_edge2<<<NEDGES / 256, 256>>>(ei);

    // streaming log-softmax-mean over the virtual [N,N] matrix
    k_msgout<<<NAGENTS / MS_ROWS, 256, MS_SMEM>>>(g2w, g2b, out);
}

// round 9
// speedup vs baseline: 1.2882x; 1.2882x over previous
#include <cuda_runtime.h>
#include <cuda_bf16.h>
#include <cstdint>

// ---------------------------------------------------------------------------
// Sizes (fixed by the problem)
// ---------------------------------------------------------------------------
#define BATCH    256
#define NAGENTS  8192
#define NEDGES   262144
#define ACT      21

#define L2E 1.4426950408889634f
#define LN2 0.6931471805599453f

// ---------------------------------------------------------------------------
// Scratch (device globals: no allocation allowed)
// ---------------------------------------------------------------------------
__device__ __align__(16) float g_h2t[1024 * BATCH];   // conv2 out, TRANSPOSED [k][m]
__device__ __align__(16) float g_wt[1024 * 512];      // fc_w transposed [k][n]
__device__ __align__(16) float g_part[4 * BATCH * 512]; // split-K partials
__device__ __align__(16) float g_hidden[BATCH * 512]; // fc out
__device__ float  g_enc[NAGENTS];             // actor_encoding[0]
__device__ float  g_deg[NAGENTS];
__device__ float  g_dinv[NAGENTS];
__device__ __align__(16) float2 g_AB[NAGENTS];  // rank-2 gcn1 aggregates
__device__ __align__(16) float  g_g1[NAGENTS * 16];
__device__ __align__(16) float  g_s[NAGENTS * 16]; // gcn2 input aggregates
__device__ float  g_w2sum[16];
__device__ float  g_b2mean;

// ---------------------------------------------------------------------------
// helpers
// ---------------------------------------------------------------------------
__device__ __forceinline__ unsigned long long fma2(unsigned long long a,
                                                   unsigned long long b,
                                                   unsigned long long c) {
    unsigned long long d;
    asm("fma.rn.f32x2 %0, %1, %2, %3;" : "=l"(d) : "l"(a), "l"(b), "l"(c));
    return d;
}
__device__ __forceinline__ unsigned long long dup2(float v) {
    unsigned u = __float_as_uint(v);
    return ((unsigned long long)u << 32) | (unsigned long long)u;
}
__device__ __forceinline__ unsigned long long pack2(float lo, float hi) {
    return ((unsigned long long)__float_as_uint(hi) << 32) |
           (unsigned long long)__float_as_uint(lo);
}
__device__ __forceinline__ float flo(unsigned long long v) {
    return __uint_as_float((unsigned)v);
}
__device__ __forceinline__ float fhi(unsigned long long v) {
    return __uint_as_float((unsigned)(v >> 32));
}
__device__ __forceinline__ float ex2(float v) {
    float r;
    asm("ex2.approx.ftz.f32 %0, %1;" : "=f"(r) : "f"(v));
    return r;
}
__device__ __forceinline__ void red4(float* p, float a, float b, float c,
                                     float d) {
    asm volatile("red.global.add.v4.f32 [%0], {%1, %2, %3, %4};"
                 :: "l"(p), "f"(a), "f"(b), "f"(c), "f"(d) : "memory");
}
__device__ __forceinline__ void red2(float* p, float a, float b) {
    asm volatile("red.global.add.v2.f32 [%0], {%1, %2};"
                 :: "l"(p), "f"(a), "f"(b) : "memory");
}

// ---------------------------------------------------------------------------
// Fused conv1+conv2 per batch element. One CTA per batch.
// Writes h2 TRANSPOSED: g_h2t[feature][batch] for the GEMM that follows.
// ---------------------------------------------------------------------------
#define CV_XS    0
#define CV_H1    848
#define CV_W2    2000
#define CV_FLOATS (2000 + 288 * 65)
#define CV_SMEM   (CV_FLOATS * 4)

__global__ void __launch_bounds__(256) k_convs(const float* __restrict__ x,
                                               const float* __restrict__ c1w,
                                               const float* __restrict__ c1b,
                                               const float* __restrict__ c2w,
                                               const float* __restrict__ c2b) {
    extern __shared__ float sm[];
    float* xs  = sm + CV_XS;
    float* h1s = sm + CV_H1;
    float* w2s = sm + CV_W2;
    const int b = blockIdx.x, tid = threadIdx.x;

    for (int i = tid; i < 845; i += 256) xs[i] = x[b * 845 + i];
    for (int i = tid; i < 64 * 288; i += 256) {
        int oc = i / 288, j = i % 288;
        w2s[j * 65 + oc] = c2w[i];
    }
    __syncthreads();

    // conv1
    for (int idx = tid; idx < 1152; idx += 256) {
        int oc = idx / 36, p = idx % 36;
        int oy = p / 6, ox = p % 6;
        const float* wb = c1w + oc * 45;
        float acc = c1b[oc];
#pragma unroll
        for (int ic = 0; ic < 5; ic++)
#pragma unroll
            for (int ky = 0; ky < 3; ky++)
#pragma unroll
                for (int kx = 0; kx < 3; kx++)
                    acc += xs[ic * 169 + (2 * oy + ky) * 13 + 2 * ox + kx] *
                           wb[ic * 9 + ky * 3 + kx];
        h1s[idx] = fmaxf(acc, 0.0f);
    }
    __syncthreads();

    // conv2: thread -> (oc = tid/4, oy = tid%4), 4 outputs along ox
    int oc = tid >> 2, oy = tid & 3;
    float bias = c2b[oc];
    float acc[4];
#pragma unroll
    for (int q = 0; q < 4; q++) acc[q] = bias;

    for (int ic = 0; ic < 32; ic++) {
#pragma unroll
        for (int ky = 0; ky < 3; ky++) {
            const float* row = &h1s[ic * 36 + (oy + ky) * 6];
            float r0 = row[0], r1 = row[1], r2 = row[2];
            float r3 = row[3], r4 = row[4], r5 = row[5];
            const float* wr = &w2s[(ic * 9 + ky * 3) * 65 + oc];
            float w0 = wr[0], w1 = wr[65], w2 = wr[130];
            acc[0] += r0 * w0 + r1 * w1 + r2 * w2;
            acc[1] += r1 * w0 + r2 * w1 + r3 * w2;
            acc[2] += r2 * w0 + r3 * w1 + r4 * w2;
            acc[3] += r3 * w0 + r4 * w1 + r5 * w2;
        }
    }
    int f0 = oc * 16 + oy * 4;
#pragma unroll
    for (int q = 0; q < 4; q++)
        g_h2t[(f0 + q) * BATCH + b] = fmaxf(acc[q], 0.0f);
}

// ---------------------------------------------------------------------------
// Transpose fc_w [512][1024] -> g_wt [1024][512]. 32x32 tiles.
// ---------------------------------------------------------------------------
__global__ void __launch_bounds__(256) k_wt(const float* __restrict__ fc_w) {
    __shared__ float t[32][33];
    const int bk = blockIdx.x & 31;   // 32 k-tiles
    const int bn = blockIdx.x >> 5;   // 16 n-tiles
    const int tx = threadIdx.x & 31, ty = threadIdx.x >> 5;  // 32 x 8
#pragma unroll
    for (int i = 0; i < 32; i += 8)
        t[ty + i][tx] = fc_w[(bn * 32 + ty + i) * 1024 + bk * 32 + tx];
    __syncthreads();
#pragma unroll
    for (int i = 0; i < 32; i += 8)
        g_wt[(bk * 32 + ty + i) * 512 + bn * 32 + tx] = t[tx][ty + i];
}

// ---------------------------------------------------------------------------
// fc GEMM: part[ks] += h2t[kslice]^T x wt[kslice].  C = [256 x 512].
// BM=BN=BK=64, split-K=4 -> 128 CTAs (one wave), 128 threads, 8x4 microtile,
// f32x2 accumulation, all SMEM staging is aligned float4 (no transposes).
// ---------------------------------------------------------------------------
__global__ void __launch_bounds__(128) k_fc_gemm() {
    __shared__ float As[64 * 64];   // [k][m]
    __shared__ float Bs[64 * 64];   // [k][n]
    const int bx = blockIdx.x;
    const int ks = bx >> 5;
    const int mt = (bx >> 3) & 3;
    const int nt = bx & 7;
    const int m0 = mt * 64, n0 = nt * 64;
    const int t  = threadIdx.x;
    const int tc = t & 15, tr = t >> 4;   // tc: 4-col group, tr: 8-row group

    unsigned long long acc[4][4];
#pragma unroll
    for (int p = 0; p < 4; p++)
#pragma unroll
        for (int j = 0; j < 4; j++) acc[p][j] = 0ull;

    const float4* A4g = (const float4*)g_h2t;
    const float4* B4g = (const float4*)g_wt;
    float4* As4w = (float4*)As;
    float4* Bs4w = (float4*)Bs;

    for (int c = 0; c < 4; c++) {
        int k0 = ks * 256 + c * 64;
        __syncthreads();
#pragma unroll
        for (int j = 0; j < 8; j++) {
            int idx = t + 128 * j;           // 0..1023
            int kk = idx >> 4, q = idx & 15;
            As4w[kk * 16 + q] = A4g[((k0 + kk) * BATCH + m0) / 4 + q];
            Bs4w[kk * 16 + q] = B4g[((k0 + kk) * 512 + n0) / 4 + q];
        }
        __syncthreads();

        const float4* As4 = (const float4*)As;
        const float4* Bs4 = (const float4*)Bs;
#pragma unroll 8
        for (int k = 0; k < 64; k++) {
            float4 a0 = As4[k * 16 + tr * 2];
            float4 a1 = As4[k * 16 + tr * 2 + 1];
            float4 bv = Bs4[k * 16 + tc];
            unsigned long long ap[4] = {pack2(a0.x, a0.y), pack2(a0.z, a0.w),
                                        pack2(a1.x, a1.y), pack2(a1.z, a1.w)};
            unsigned long long bd[4] = {dup2(bv.x), dup2(bv.y),
                                        dup2(bv.z), dup2(bv.w)};
#pragma unroll
            for (int p = 0; p < 4; p++)
#pragma unroll
                for (int j = 0; j < 4; j++)
                    acc[p][j] = fma2(ap[p], bd[j], acc[p][j]);
        }
    }

    float* outp = g_part + ks * (BATCH * 512);
#pragma unroll
    for (int p = 0; p < 4; p++) {
        int rlo = m0 + tr * 8 + 2 * p;
        float4 vlo = make_float4(flo(acc[p][0]), flo(acc[p][1]),
                                 flo(acc[p][2]), flo(acc[p][3]));
        float4 vhi = make_float4(fhi(acc[p][0]), fhi(acc[p][1]),
                                 fhi(acc[p][2]), fhi(acc[p][3]));
        *(float4*)(outp + rlo * 512 + n0 + tc * 4) = vlo;
        *(float4*)(outp + (rlo + 1) * 512 + n0 + tc * 4) = vhi;
    }
}

// Epilogue: sum 4 split-K slabs + bias, relu -> g_hidden.
__global__ void __launch_bounds__(256) k_fcsum(const float* __restrict__ fc_b) {
    int gid = blockIdx.x * 256 + threadIdx.x;   // 0..32767 float4s
    const float4* p4 = (const float4*)g_part;
    float4 a = p4[gid];
    float4 b = p4[32768 + gid];
    float4 c = p4[65536 + gid];
    float4 d = p4[98304 + gid];
    float4 bias = ((const float4*)fc_b)[gid & 127];
    float4 r;
    r.x = fmaxf(a.x + b.x + c.x + d.x + bias.x, 0.0f);
    r.y = fmaxf(a.y + b.y + c.y + d.y + bias.y, 0.0f);
    r.z = fmaxf(a.z + b.z + c.z + d.z + bias.z, 0.0f);
    r.w = fmaxf(a.w + b.w + c.w + d.w + bias.w, 0.0f);
    ((float4*)g_hidden)[gid] = r;
}

// ---------------------------------------------------------------------------
// logits + categorical log_prob / entropy; writes action as float.
// Output layout: [action(256) | msg_out(8192) | log_prob(256) | entropy(256)]
// ---------------------------------------------------------------------------
__global__ void __launch_bounds__(256) k_logits(const float* __restrict__ muw,
                                                const float* __restrict__ mub,
                                                const int* __restrict__ action,
                                                float* __restrict__ out) {
    __shared__ float hs[512];
    __shared__ float lg[24];
    const int bb = blockIdx.x, tid = threadIdx.x;
    const int wid = tid >> 5, lane = tid & 31;

    ((float2*)hs)[tid] = ((const float2*)(g_hidden + bb * 512))[tid];
    __syncthreads();

    const float4* h4 = (const float4*)hs;
    for (int a = wid; a < ACT; a += 8) {
        const float4* wr = (const float4*)(muw + a * 512);
        float acc = 0.0f;
#pragma unroll
        for (int i = 0; i < 4; i++) {
            float4 w = wr[lane + i * 32];
            float4 h = h4[lane + i * 32];
            acc += w.x * h.x + w.y * h.y + w.z * h.z + w.w * h.w;
        }
#pragma unroll
        for (int o = 16; o; o >>= 1) acc += __shfl_xor_sync(0xffffffffu, acc, o);
        if (lane == 0) lg[a] = acc + mub[a];
    }
    __syncthreads();

    if (wid == 0) {
        float l = (lane < ACT) ? lg[lane] : -3.4e38f;
        float m = l;
#pragma unroll
        for (int o = 16; o; o >>= 1)
            m = fmaxf(m, __shfl_xor_sync(0xffffffffu, m, o));
        float e  = (lane < ACT) ? __expf(l - m) : 0.0f;
        float el = (lane < ACT) ? e * l : 0.0f;
        float se = e, sel = el;
#pragma unroll
        for (int o = 16; o; o >>= 1) {
            se  += __shfl_xor_sync(0xffffffffu, se, o);
            sel += __shfl_xor_sync(0xffffffffu, sel, o);
        }
        int a = action[bb];
        float la = __shfl_sync(0xffffffffu, l, a);
        if (lane == 0) {
            float lse = m + __logf(se);
            out[BATCH + NAGENTS + bb]     = la - lse;        // log_prob
            out[2 * BATCH + NAGENTS + bb] = lse - sel / se;  // entropy
            out[bb] = (float)a;                              // action
        }
    }
}

// ---------------------------------------------------------------------------
// actor_encoding row 0: enc[j] = hidden[0] . msg_w[j] + msg_b[j]. Warp-dot.
// ---------------------------------------------------------------------------
__global__ void __launch_bounds__(256) k_enc(const float* __restrict__ msg_w,
                                             const float* __restrict__ msg_b) {
    int gtid = blockIdx.x * 256 + threadIdx.x;
    int j    = gtid >> 5;
    int lane = gtid & 31;
    if (j >= NAGENTS) return;
    const float4* w4 = (const float4*)(msg_w + j * 512);
    const float4* h4 = (const float4*)g_hidden;
    float acc = 0.0f;
#pragma unroll
    for (int i = 0; i < 4; i++) {
        float4 w = w4[lane + i * 32];
        float4 h = h4[lane + i * 32];
        acc += w.x * h.x + w.y * h.y + w.z * h.z + w.w * h.w;
    }
#pragma unroll
    for (int o = 16; o; o >>= 1) acc += __shfl_xor_sync(0xffffffffu, acc, o);
    if (lane == 0) g_enc[j] = acc + msg_b[j];
}

// ---------------------------------------------------------------------------
// blocks 0-15: colsum(W2); block 16: mean(b2); blocks 17-48: deg init.
// ---------------------------------------------------------------------------
__global__ void k_w2sum(const float* __restrict__ W2,
                        const float* __restrict__ b2) {
    int tid = threadIdx.x;
    int k   = blockIdx.x;
    if (k >= 17) {
        int i = (k - 17) * 256 + tid;
        if (i < NAGENTS) g_deg[i] = 1.0f;   // self loop
        return;
    }
    __shared__ float red[256];
    const float* src = (k < 16) ? (W2 + k * NAGENTS) : b2;
    float acc = 0.0f;
    for (int j = tid; j < NAGENTS; j += 256) acc += src[j];
    red[tid] = acc;
    __syncthreads();
    for (int s = 128; s; s >>= 1) {
        if (tid < s) red[tid] += red[tid + s];
        __syncthreads();
    }
    if (tid == 0) {
        if (k < 16) g_w2sum[k] = red[0];
        else        g_b2mean  = red[0] * (1.0f / (float)NAGENTS);
    }
}

// ---------------------------------------------------------------------------
// GCN norm + aggregation
// ---------------------------------------------------------------------------
__global__ void k_deg(const int* __restrict__ ei) {
    int e = blockIdx.x * 256 + threadIdx.x;
    if (e < NEDGES) atomicAdd(&g_deg[ei[2 * e + 1]], 1.0f);
}
__global__ void k_dinvAB(const float* __restrict__ xm) {
    int i = blockIdx.x * 256 + threadIdx.x;
    if (i >= NAGENTS) return;
    float dv = rsqrtf(g_deg[i]);
    g_dinv[i] = dv;
    float d2 = dv * dv;                       // self-loop norm
    g_AB[i] = make_float2(d2 * xm[i], d2 * g_enc[i]);
}
__global__ void k_edge1(const int* __restrict__ ei,
                        const float* __restrict__ xm) {
    int e = blockIdx.x * 256 + threadIdx.x;
    if (e >= NEDGES) return;
    int s = ei[2 * e], d = ei[2 * e + 1];
    float nrm = g_dinv[s] * g_dinv[d];
    red2((float*)&g_AB[d], nrm * xm[s], nrm * g_enc[s]);
}
// g1 = relu(AB @ W1 + b1); s initialized with the self-loop term d^2 * g1
__global__ void k_g1s(const float* __restrict__ w1,
                      const float* __restrict__ b1) {
    int idx = blockIdx.x * 256 + threadIdx.x;
    if (idx >= NAGENTS * 16) return;
    int i = idx >> 4, k = idx & 15;
    float2 ab = g_AB[i];
    float v = fmaxf(ab.x * w1[k] + ab.y * w1[16 + k] + b1[k], 0.0f);
    g_g1[idx] = v;
    float dv = g_dinv[i];
    g_s[idx] = dv * dv * v;
}
__global__ void k_edge2(const int* __restrict__ ei) {
    int e = blockIdx.x * 256 + threadIdx.x;
    if (e >= NEDGES) return;
    int s = ei[2 * e], d = ei[2 * e + 1];
    float nrm = g_dinv[s] * g_dinv[d];
    const float4* g1r = (const float4*)(g_g1 + s * 16);
    float* sd = g_s + d * 16;
#pragma unroll
    for (int q = 0; q < 4; q++) {
        float4 v = g1r[q];
        red4(sd + q * 4, nrm * v.x, nrm * v.y, nrm * v.z, nrm * v.w);
    }
}

// ---------------------------------------------------------------------------
// K12: msg_out[i] = mean_j(g_ij) - lse_j(g_ij) with g_ij = s[i].W2[:,j]+b2[j].
// 16 rows/CTA, W2 streamed in 16x1024 SMEM chunks, f32x2 FMA.
// log2-domain accumulation (s, b2 pre-scaled by log2 e) -> raw ex2, no
// max-tracking needed (|g| bounded analytically far below overflow).
// ---------------------------------------------------------------------------
#define MS_CHUNK 1024
#define MS_ROWS  16
#define MS_SMEM  (16 * MS_CHUNK * 4 + MS_ROWS * 16 * 8)

__global__ void __launch_bounds__(256) k_msgout(const float* __restrict__ W2,
                                                const float* __restrict__ b2,
                                                float* __restrict__ out) {
    extern __shared__ char smraw[];
    float* wsm = (float*)smraw;                                    // 16*1024 f
    unsigned long long* sdup =
        (unsigned long long*)(smraw + 16 * MS_CHUNK * 4);          // 256 u64

    const int tid  = threadIdx.x;
    const int row0 = blockIdx.x * MS_ROWS;

    {   // duplicated, log2e-scaled s values for f32x2 broadcast
        int r = tid >> 4, k = tid & 15;
        sdup[tid] = dup2(g_s[(row0 + r) * 16 + k] * L2E);
    }

    float sr[MS_ROWS];
#pragma unroll
    for (int r = 0; r < MS_ROWS; r++) sr[r] = 0.0f;

    const float4* gw4 = (const float4*)W2;

    for (int chunk = 0; chunk < NAGENTS / MS_CHUNK; chunk++) {
        int base = chunk * MS_CHUNK;
        __syncthreads();
#pragma unroll
        for (int k = 0; k < 16; k++)
            ((float4*)wsm)[k * 256 + tid] = gw4[(k * NAGENTS + base) / 4 + tid];
        float4 bb = ((const float4*)(b2 + base))[tid];
        __syncthreads();

        unsigned long long acc0[MS_ROWS], acc1[MS_ROWS];
        unsigned long long b01 = pack2(bb.x * L2E, bb.y * L2E);
        unsigned long long b23 = pack2(bb.z * L2E, bb.w * L2E);
#pragma unroll
        for (int r = 0; r < MS_ROWS; r++) { acc0[r] = b01; acc1[r] = b23; }

        const ulonglong2* wU2 = (const ulonglong2*)wsm;
#pragma unroll
        for (int k = 0; k < 16; k++) {
            ulonglong2 w = wU2[k * 256 + tid];    // LDS.128, conflict-free
#pragma unroll
            for (int r = 0; r < MS_ROWS; r++) {
                unsigned long long sv = sdup[r * 16 + k];  // broadcast
                acc0[r] = fma2(w.x, sv, acc0[r]);
                acc1[r] = fma2(w.y, sv, acc1[r]);
            }
        }
#pragma unroll
        for (int r = 0; r < MS_ROWS; r++) {
            sr[r] += ex2(flo(acc0[r])) + ex2(fhi(acc0[r])) +
                     ex2(flo(acc1[r])) + ex2(fhi(acc1[r]));
        }
    }

    // block sum-reduce per row; alias onto wsm (16KB)
    __syncthreads();
    float* rs = wsm;              // [16][256]
#pragma unroll
    for (int r = 0; r < MS_ROWS; r++) rs[r * 256 + tid] = sr[r];
    for (int step = 128; step > 0; step >>= 1) {
        __syncthreads();
        if (tid < step) {
#pragma unroll
            for (int r = 0; r < MS_ROWS; r++)
                rs[r * 256 + tid] += rs[r * 256 + tid + step];
        }
    }
    __syncthreads();
    if (tid < MS_ROWS) {
        int row = row0 + tid;
        float lse = LN2 * __log2f(rs[tid * 256]);
        float acc = 0.0f;
#pragma unroll
        for (int k = 0; k < 16; k++) acc += g_s[row * 16 + k] * g_w2sum[k];
        out[BATCH + row] = acc * (1.0f / (float)NAGENTS) + g_b2mean - lse;
    }
}

// ---------------------------------------------------------------------------
// launch
// ---------------------------------------------------------------------------
extern "C" void kernel_launch(void* const* d_in, const int* in_sizes, int n_in,
                              void* d_out, int out_size) {
    const float* x    = (const float*)d_in[0];
    const float* xmsg = (const float*)d_in[1];
    const int*   ei   = (const int*)d_in[2];
    const int*   act  = (const int*)d_in[3];
    const float* c1w  = (const float*)d_in[4];
    const float* c1b  = (const float*)d_in[5];
    const float* c2w  = (const float*)d_in[6];
    const float* c2b  = (const float*)d_in[7];
    const float* fcw  = (const float*)d_in[8];
    const float* fcb  = (const float*)d_in[9];
    const float* muw  = (const float*)d_in[10];
    const float* mub  = (const float*)d_in[11];
    const float* msw  = (const float*)d_in[12];
    const float* msb  = (const float*)d_in[13];
    const float* g1w  = (const float*)d_in[14];
    const float* g1b  = (const float*)d_in[15];
    const float* g2w  = (const float*)d_in[16];
    const float* g2b  = (const float*)d_in[17];
    float* out = (float*)d_out;

    cudaFuncSetAttribute(k_convs, cudaFuncAttributeMaxDynamicSharedMemorySize,
                         CV_SMEM);
    cudaFuncSetAttribute(k_msgout, cudaFuncAttributeMaxDynamicSharedMemorySize,
                         MS_SMEM);

    // Independent preprocessing
    k_wt<<<512, 256>>>(fcw);
    k_w2sum<<<49, 256>>>(g2w, g2b);
    k_deg<<<NEDGES / 256, 256>>>(ei);

    // CNN / actor head
    k_convs<<<BATCH, 256, CV_SMEM>>>(x, c1w, c1b, c2w, c2b);
    k_fc_gemm<<<128, 128>>>();
    k_fcsum<<<128, 256>>>(fcb);
    k_logits<<<BATCH, 256>>>(muw, mub, act, out);
    k_enc<<<NAGENTS / 8, 256>>>(msw, msb);

    // GCN
    k_dinvAB<<<NAGENTS / 256, 256>>>(xmsg);
    k_edge1<<<NEDGES / 256, 256>>>(ei, xmsg);
    k_g1s<<<NAGENTS * 16 / 256, 256>>>(g1w, g1b);
    k_edge2<<<NEDGES / 256, 256>>>(ei);

    // streaming log-softmax-mean over the virtual [N,N] matrix
    k_msgout<<<NAGENTS / MS_ROWS, 256, MS_SMEM>>>(g2w, g2b, out);
}